// round 1
// baseline (speedup 1.0000x reference)
#include <cuda_runtime.h>

#define TWO_PI 6.283185307179586f

__device__ __forceinline__ float2 cmulf(float2 a, float2 b) {
    return make_float2(fmaf(a.x, b.x, -a.y * b.y), fmaf(a.x, b.y, a.y * b.x));
}

// Scratch: frequency-domain tensors.
// x_f: (16*32) images x 256 x 129 complex  = 16,908,288 float2 (135 MB)
// k_f: (32*32) images x 256 x 129 complex  = 33,816,576 float2 (270 MB)
// o_f: (16*32) images x 256 x 129 complex  = 16,908,288 float2 (135 MB)
__device__ float2 g_xf[16908288];
__device__ float2 g_kf[33816576];
__device__ float2 g_of[16908288];

// ---------------------------------------------------------------------------
// Forward real FFT along W (length 256 -> 129 bins), two rows packed per
// complex FFT. One block (128 threads) handles one row-pair.
// Stockham radix-2, 8 stages, ping-pong in smem. Result lands back in bufA.
// ---------------------------------------------------------------------------
__global__ void __launch_bounds__(128) rfft_rows_kernel(
    const float* __restrict__ in, float2* __restrict__ out)
{
    __shared__ float2 bufA[256], bufB[256];
    __shared__ float2 tw[128];
    const int t = threadIdx.x;
    const long p = blockIdx.x;

    {
        float s, c;
        sincosf(-TWO_PI * (float)t / 256.0f, &s, &c);
        tw[t] = make_float2(c, s);
    }

    const float* r = in + p * 512;  // two consecutive rows of 256
    bufA[t]       = make_float2(r[t],       r[256 + t]);
    bufA[t + 128] = make_float2(r[t + 128], r[384 + t]);
    __syncthreads();

    float2 *X = bufA, *Y = bufB;
#pragma unroll
    for (int st = 0; st < 8; st++) {
        const int s = 1 << st;
        const int m = 128 / s;          // half-length of current sub-FFT
        const int pp = t / s;
        const int q  = t - pp * s;
        float2 a = X[q + s * pp];
        float2 b = X[q + s * (pp + m)];
        float2 w = tw[pp * s];
        float2 d = make_float2(a.x - b.x, a.y - b.y);
        Y[q + 2 * s * pp]     = make_float2(a.x + b.x, a.y + b.y);
        Y[q + 2 * s * pp + s] = cmulf(d, w);
        __syncthreads();
        float2* tmp = X; X = Y; Y = tmp;
    }

    // Split packed spectrum: Z = FFT(r0 + i*r1)
    // X0[k] = (Z[k] + conj(Z[N-k]))/2 ; X1[k] = (Z[k] - conj(Z[N-k]))/(2i)
    float2* o = out + p * 258;  // two output rows of 129
    for (int k = t; k < 129; k += 128) {
        float2 zk = X[k];
        float2 zm = X[(256 - k) & 255];
        o[k]       = make_float2(0.5f * (zk.x + zm.x),  0.5f * (zk.y - zm.y));
        o[129 + k] = make_float2(0.5f * (zk.y + zm.y), -0.5f * (zk.x - zm.x));
    }
}

// ---------------------------------------------------------------------------
// Complex FFT along H (length 256) over columns of a (256 x 129) image.
// SIGN = -1 forward, +1 inverse (unnormalized). 8 columns per block, in-place.
// ---------------------------------------------------------------------------
template <int SIGN>
__global__ void __launch_bounds__(256) fft_cols_kernel(float2* __restrict__ data)
{
    __shared__ float2 bufA[2048], bufB[2048];
    __shared__ float2 tw[128];
    const int t = threadIdx.x;

    if (t < 128) {
        float s, c;
        sincosf((float)SIGN * TWO_PI * (float)t / 256.0f, &s, &c);
        tw[t] = make_float2(c, s);
    }

    float2* img = data + (size_t)blockIdx.y * 33024;
    const int col0 = blockIdx.x * 8;

    for (int idx = t; idx < 2048; idx += 256) {
        int h = idx >> 3, c = idx & 7;
        int col = col0 + c;
        bufA[idx] = (col < 129) ? img[h * 129 + col] : make_float2(0.f, 0.f);
    }
    __syncthreads();

    float2 *X = bufA, *Y = bufB;
#pragma unroll
    for (int st = 0; st < 8; st++) {
        const int s = 1 << st;
        const int m = 128 / s;
#pragma unroll
        for (int r4 = 0; r4 < 4; r4++) {
            int j = t + r4 * 256;
            int c = j & 7, u = j >> 3;
            int pp = u / s, q = u - pp * s;
            float2 a = X[(q + s * pp) * 8 + c];
            float2 b = X[(q + s * (pp + m)) * 8 + c];
            float2 w = tw[pp * s];
            float2 d = make_float2(a.x - b.x, a.y - b.y);
            Y[(q + 2 * s * pp) * 8 + c]     = make_float2(a.x + b.x, a.y + b.y);
            Y[(q + 2 * s * pp + s) * 8 + c] = cmulf(d, w);
        }
        __syncthreads();
        float2* tmp = X; X = Y; Y = tmp;
    }

    for (int idx = t; idx < 2048; idx += 256) {
        int h = idx >> 3, c = idx & 7;
        int col = col0 + c;
        if (col < 129) img[h * 129 + col] = X[idx];
    }
}

// ---------------------------------------------------------------------------
// Pointwise frequency contraction: per bin f, out[b,o] = sum_c x[b,c]*k[o,c].
// 8 bins per block. x tile staged with per-b pad (stride 258 float2) so the
// 4-b-group x loads are bank-conflict-free; k loads broadcast within warp.
// Each thread: 4b x 4o register tile for one bin.
// ---------------------------------------------------------------------------
__global__ void __launch_bounds__(256) pointwise_kernel(
    const float2* __restrict__ xf, const float2* __restrict__ kf,
    float2* __restrict__ of)
{
    extern __shared__ float2 sm[];
    float2* xs = sm;          // 16 * 258 = 4128 float2 (padded)
    float2* ks = sm + 4128;   // 32*32*8 = 8192 float2
    const int t = threadIdx.x;
    const long f0 = (long)blockIdx.x * 8;

    for (int idx = t; idx < 4096; idx += 256) {
        int row = idx >> 3, fi = idx & 7;    // row = b*32+c
        int b = row >> 5, c = row & 31;
        xs[b * 258 + c * 8 + fi] = xf[(size_t)row * 33024 + f0 + fi];
    }
    for (int idx = t; idx < 8192; idx += 256) {
        int row = idx >> 3, fi = idx & 7;    // row = o*32+c
        ks[idx] = kf[(size_t)row * 33024 + f0 + fi];
    }
    __syncthreads();

    const int fi = t & 7;
    const int g  = t >> 3;            // 0..31
    const int b0 = (g & 3) * 4;       // {0,4,8,12}
    const int o0 = (g >> 2) * 4;      // {0,4,...,28}

    float2 acc[4][4];
#pragma unroll
    for (int i = 0; i < 4; i++)
#pragma unroll
        for (int j = 0; j < 4; j++) acc[i][j] = make_float2(0.f, 0.f);

    for (int c = 0; c < 32; c++) {
        float2 xv[4], kv[4];
#pragma unroll
        for (int i = 0; i < 4; i++) xv[i] = xs[(b0 + i) * 258 + c * 8 + fi];
#pragma unroll
        for (int j = 0; j < 4; j++) kv[j] = ks[((o0 + j) * 32 + c) * 8 + fi];
#pragma unroll
        for (int i = 0; i < 4; i++)
#pragma unroll
            for (int j = 0; j < 4; j++) {
                acc[i][j].x = fmaf(xv[i].x, kv[j].x, fmaf(-xv[i].y, kv[j].y, acc[i][j].x));
                acc[i][j].y = fmaf(xv[i].x, kv[j].y, fmaf( xv[i].y, kv[j].x, acc[i][j].y));
            }
    }

#pragma unroll
    for (int i = 0; i < 4; i++)
#pragma unroll
        for (int j = 0; j < 4; j++)
            of[(size_t)((b0 + i) * 32 + (o0 + j)) * 33024 + f0 + fi] = acc[i][j];
}

// ---------------------------------------------------------------------------
// Inverse real FFT along W: two output rows unpacked from one inverse complex
// FFT (Hermitian-extended input). Applies final 1/(256*256) scaling.
// ---------------------------------------------------------------------------
__global__ void __launch_bounds__(128) irfft_rows_kernel(
    const float2* __restrict__ in, float* __restrict__ out)
{
    __shared__ float2 bufA[256], bufB[256];
    __shared__ float2 tw[128];
    const int t = threadIdx.x;
    const long p = blockIdx.x;

    {
        float s, c;
        sincosf(TWO_PI * (float)t / 256.0f, &s, &c);
        tw[t] = make_float2(c, s);
    }

    const float2* X0 = in + p * 258;
    const float2* X1 = X0 + 129;
    // Z[k] = X0[k] + i*X1[k], Hermitian-extend for k>128
    for (int k = t; k < 256; k += 128) {
        float2 a, b;
        if (k <= 128) { a = X0[k]; b = X1[k]; }
        else {
            float2 a0 = X0[256 - k]; a = make_float2(a0.x, -a0.y);
            float2 b0 = X1[256 - k]; b = make_float2(b0.x, -b0.y);
        }
        bufA[k] = make_float2(a.x - b.y, a.y + b.x);
    }
    __syncthreads();

    float2 *X = bufA, *Y = bufB;
#pragma unroll
    for (int st = 0; st < 8; st++) {
        const int s = 1 << st;
        const int m = 128 / s;
        const int pp = t / s;
        const int q  = t - pp * s;
        float2 a = X[q + s * pp];
        float2 b = X[q + s * (pp + m)];
        float2 w = tw[pp * s];
        float2 d = make_float2(a.x - b.x, a.y - b.y);
        Y[q + 2 * s * pp]     = make_float2(a.x + b.x, a.y + b.y);
        Y[q + 2 * s * pp + s] = cmulf(d, w);
        __syncthreads();
        float2* tmp = X; X = Y; Y = tmp;
    }

    const float sc = 1.0f / 65536.0f;  // 1/(H*W)
    float* o = out + p * 512;
    o[t]           = X[t].x * sc;
    o[t + 128]     = X[t + 128].x * sc;
    o[256 + t]     = X[t].y * sc;
    o[384 + t]     = X[t + 128].y * sc;
}

// ---------------------------------------------------------------------------
extern "C" void kernel_launch(void* const* d_in, const int* in_sizes, int n_in,
                              void* d_out, int out_size)
{
    const float* x = (const float*)d_in[0];   // (16,32,256,256)
    const float* w = (const float*)d_in[1];   // (32,32,256,256)
    float* out = (float*)d_out;               // (16,32,256,256)

    float2 *pxf, *pkf, *pof;
    cudaGetSymbolAddress((void**)&pxf, g_xf);
    cudaGetSymbolAddress((void**)&pkf, g_kf);
    cudaGetSymbolAddress((void**)&pof, g_of);

    cudaFuncSetAttribute(pointwise_kernel,
                         cudaFuncAttributeMaxDynamicSharedMemorySize, 98560);

    // Forward rFFT along W (packed pairs): x has 16*32*256/2 = 65536 pairs,
    // w has 32*32*256/2 = 131072 pairs.
    rfft_rows_kernel<<<65536, 128>>>(x, pxf);
    rfft_rows_kernel<<<131072, 128>>>(w, pkf);

    // Forward FFT along H: 17 column-tiles of 8 per image.
    fft_cols_kernel<-1><<<dim3(17, 512), 256>>>(pxf);
    fft_cols_kernel<-1><<<dim3(17, 1024), 256>>>(pkf);

    // Per-bin channel contraction: 33024 bins / 8 per block.
    pointwise_kernel<<<4128, 256, 98560>>>(pxf, pkf, pof);

    // Inverse FFT along H, then inverse rFFT along W (with 1/(H*W) scale).
    fft_cols_kernel<1><<<dim3(17, 512), 256>>>(pof);
    irfft_rows_kernel<<<65536, 128>>>(pof, out);
}

// round 2
// speedup vs baseline: 1.2341x; 1.2341x over previous
#include <cuda_runtime.h>

#define TWO_PI 6.283185307179586f

typedef unsigned long long u64;

__device__ __forceinline__ float2 cmulf(float2 a, float2 b) {
    return make_float2(fmaf(a.x, b.x, -a.y * b.y), fmaf(a.x, b.y, a.y * b.x));
}
__device__ __forceinline__ float2 cadd(float2 a, float2 b) { return make_float2(a.x+b.x, a.y+b.y); }
__device__ __forceinline__ float2 csub(float2 a, float2 b) { return make_float2(a.x-b.x, a.y-b.y); }

// padded smem index for row-FFT buffers (≤2-way banks on all stages)
__device__ __forceinline__ int rphys(int i) { return i + 5 * (i >> 4); }
// padded smem index for col-FFT buffers: 8-wide interleave + 8 pad per 4 rows
__device__ __forceinline__ int cphys(int e, int c) { return e * 8 + c + 8 * (e >> 2); }

__device__ __forceinline__ u64 pk2(float lo, float hi) {
    u64 r; asm("mov.b64 %0, {%1, %2};" : "=l"(r) : "f"(lo), "f"(hi)); return r;
}
__device__ __forceinline__ u64 ffma2(u64 a, u64 b, u64 c) {
    u64 d; asm("fma.rn.f32x2 %0, %1, %2, %3;" : "=l"(d) : "l"(a), "l"(b), "l"(c)); return d;
}
__device__ __forceinline__ float2 upk2(u64 v) {
    float x, y; asm("mov.b64 {%0, %1}, %2;" : "=f"(x), "=f"(y) : "l"(v)); return make_float2(x, y);
}

// Scratch frequency-domain tensors.
__device__ float2 g_xf[16908288];   // (16*32) x 256 x 129
__device__ float2 g_kf[33816576];   // (32*32) x 256 x 129
__device__ float2 g_of[16908288];   // (16*32) x 256 x 129

// ---------------------------------------------------------------------------
// Fused radix-4 Stockham stage (composition of two radix-2 stages).
// u in [0,64), s in {1,4,16,64}. Reads X[u + 64k], writes 4 scattered outputs.
// ---------------------------------------------------------------------------
#define BF4(SIGN, LOAD, STORE)                                                 \
    {                                                                          \
        const int q  = u & (s - 1);                                            \
        const int ps = u - q;                                                  \
        float2 w1 = tw[ps], w2 = tw[2 * ps];                                   \
        float2 a1 = LOAD(u), a2 = LOAD(u + 64);                                \
        float2 b1 = LOAD(u + 128), b2 = LOAD(u + 192);                         \
        float2 u0 = cadd(a1, b1), u1 = cmulf(csub(a1, b1), w1);                \
        float2 v0 = cadd(a2, b2), v1 = cmulf(csub(a2, b2), w1);                \
        v1 = (SIGN < 0) ? make_float2(v1.y, -v1.x)                             \
                        : make_float2(-v1.y, v1.x);                            \
        const int ob = u + 3 * ps;                                             \
        STORE(ob,          cadd(u0, v0));                                      \
        STORE(ob + s,      cadd(u1, v1));                                      \
        STORE(ob + 2 * s,  cmulf(csub(u0, v0), w2));                           \
        STORE(ob + 3 * s,  cmulf(csub(u1, v1), w2));                           \
    }

// ---------------------------------------------------------------------------
// Forward real FFT along W: 4 packed row-pairs per block (256 threads).
// ---------------------------------------------------------------------------
__global__ void __launch_bounds__(256) rfft_rows_kernel(
    const float* __restrict__ in, float2* __restrict__ out)
{
    __shared__ float2 bufA[4][336], bufB[4][336];
    __shared__ float2 tw[128];
    const int t = threadIdx.x;
    const int f = t >> 6, u = t & 63;

    if (t < 128) {
        float s, c;
        sincosf(-TWO_PI * (float)t / 256.0f, &s, &c);
        tw[t] = make_float2(c, s);
    }

    const long p = (long)blockIdx.x * 4 + f;
    const float* r = in + p * 512;
#pragma unroll
    for (int k = 0; k < 4; k++) {
        int w = u + 64 * k;
        bufA[f][rphys(w)] = make_float2(r[w], r[256 + w]);
    }
    __syncthreads();

    float2 *X = bufA[f], *Y = bufB[f];
#pragma unroll
    for (int st = 0; st < 4; st++) {
        const int s = 1 << (2 * st);
#define LD_R(i)     X[rphys(i)]
#define ST_R(i, v)  Y[rphys(i)] = (v)
        BF4(-1, LD_R, ST_R)
#undef LD_R
#undef ST_R
        __syncthreads();
        float2* tmp = X; X = Y; Y = tmp;
    }

    float2* o = out + p * 258;
    for (int k = u; k < 129; k += 64) {
        float2 zk = X[rphys(k)];
        float2 zm = X[rphys((256 - k) & 255)];
        o[k]       = make_float2(0.5f * (zk.x + zm.x),  0.5f * (zk.y - zm.y));
        o[129 + k] = make_float2(0.5f * (zk.y + zm.y), -0.5f * (zk.x - zm.x));
    }
}

// ---------------------------------------------------------------------------
// Complex FFT along H, 8 columns per block, radix-4.
// ---------------------------------------------------------------------------
template <int SIGN>
__global__ void __launch_bounds__(256) fft_cols_kernel(float2* __restrict__ data)
{
    __shared__ float2 bufA[2552], bufB[2552];
    __shared__ float2 tw[128];
    const int t = threadIdx.x;

    if (t < 128) {
        float s, c;
        sincosf((float)SIGN * TWO_PI * (float)t / 256.0f, &s, &c);
        tw[t] = make_float2(c, s);
    }

    float2* img = data + (size_t)blockIdx.y * 33024;
    const int col0 = blockIdx.x * 8;

    for (int idx = t; idx < 2048; idx += 256) {
        int h = idx >> 3, c = idx & 7;
        int col = col0 + c;
        bufA[cphys(h, c)] = (col < 129) ? img[h * 129 + col] : make_float2(0.f, 0.f);
    }
    __syncthreads();

    float2 *X = bufA, *Y = bufB;
#pragma unroll
    for (int st = 0; st < 4; st++) {
        const int s = 1 << (2 * st);
#pragma unroll
        for (int r2 = 0; r2 < 2; r2++) {
            int j = t + r2 * 256;
            const int c = j & 7;
            const int u = j >> 3;
#define LD_C(i)     X[cphys((i), c)]
#define ST_C(i, v)  Y[cphys((i), c)] = (v)
            BF4(SIGN, LD_C, ST_C)
#undef LD_C
#undef ST_C
        }
        __syncthreads();
        float2* tmp = X; X = Y; Y = tmp;
    }

    for (int idx = t; idx < 2048; idx += 256) {
        int h = idx >> 3, c = idx & 7;
        int col = col0 + c;
        if (col < 129) img[h * 129 + col] = X[cphys(h, c)];
    }
}

// ---------------------------------------------------------------------------
// Pointwise frequency contraction with packed f32x2 FMA.
// 8 bins/block, each thread 4b x 4o register tile for one bin.
// ---------------------------------------------------------------------------
__global__ void __launch_bounds__(256) pointwise_kernel(
    const float2* __restrict__ xf, const float2* __restrict__ kf,
    float2* __restrict__ of)
{
    extern __shared__ float2 sm[];
    float2* xs = sm;          // 16 * 258 float2 (padded)
    float2* ks = sm + 4128;   // 32*32*8 float2
    const int t = threadIdx.x;
    const long f0 = (long)blockIdx.x * 8;

    for (int idx = t; idx < 4096; idx += 256) {
        int row = idx >> 3, fi = idx & 7;
        int b = row >> 5, c = row & 31;
        xs[b * 258 + c * 8 + fi] = xf[(size_t)row * 33024 + f0 + fi];
    }
    for (int idx = t; idx < 8192; idx += 256) {
        ks[idx] = kf[(size_t)(idx >> 3) * 33024 + f0 + (idx & 7)];
    }
    __syncthreads();

    const int fi = t & 7;
    const int g  = t >> 3;
    const int b0 = (g & 3) * 4;
    const int o0 = (g >> 2) * 4;

    u64 acc[4][4];
#pragma unroll
    for (int i = 0; i < 4; i++)
#pragma unroll
        for (int j = 0; j < 4; j++) acc[i][j] = 0ULL;

    for (int c = 0; c < 32; c++) {
        u64 xa[4], xb[4], ka[4], kb[4];
#pragma unroll
        for (int i = 0; i < 4; i++) {
            float2 xv = xs[(b0 + i) * 258 + c * 8 + fi];
            xa[i] = pk2(xv.x, xv.x);
            xb[i] = pk2(-xv.y, xv.y);
        }
#pragma unroll
        for (int j = 0; j < 4; j++) {
            float2 kv = ks[((o0 + j) * 32 + c) * 8 + fi];
            ka[j] = pk2(kv.x, kv.y);
            kb[j] = pk2(kv.y, kv.x);
        }
#pragma unroll
        for (int i = 0; i < 4; i++)
#pragma unroll
            for (int j = 0; j < 4; j++) {
                acc[i][j] = ffma2(xa[i], ka[j], acc[i][j]);
                acc[i][j] = ffma2(xb[i], kb[j], acc[i][j]);
            }
    }

#pragma unroll
    for (int i = 0; i < 4; i++)
#pragma unroll
        for (int j = 0; j < 4; j++)
            of[(size_t)((b0 + i) * 32 + (o0 + j)) * 33024 + f0 + fi] = upk2(acc[i][j]);
}

// ---------------------------------------------------------------------------
// Inverse real FFT along W: 4 row-pairs per block, with 1/(H*W) scaling.
// ---------------------------------------------------------------------------
__global__ void __launch_bounds__(256) irfft_rows_kernel(
    const float2* __restrict__ in, float* __restrict__ out)
{
    __shared__ float2 bufA[4][336], bufB[4][336];
    __shared__ float2 tw[128];
    const int t = threadIdx.x;
    const int f = t >> 6, u = t & 63;

    if (t < 128) {
        float s, c;
        sincosf(TWO_PI * (float)t / 256.0f, &s, &c);
        tw[t] = make_float2(c, s);
    }

    const long p = (long)blockIdx.x * 4 + f;
    const float2* X0 = in + p * 258;
    const float2* X1 = X0 + 129;
#pragma unroll
    for (int kk = 0; kk < 4; kk++) {
        int k = u + 64 * kk;
        float2 a, b;
        if (k <= 128) { a = X0[k]; b = X1[k]; }
        else {
            float2 a0 = X0[256 - k]; a = make_float2(a0.x, -a0.y);
            float2 b0 = X1[256 - k]; b = make_float2(b0.x, -b0.y);
        }
        bufA[f][rphys(k)] = make_float2(a.x - b.y, a.y + b.x);
    }
    __syncthreads();

    float2 *X = bufA[f], *Y = bufB[f];
#pragma unroll
    for (int st = 0; st < 4; st++) {
        const int s = 1 << (2 * st);
#define LD_R(i)     X[rphys(i)]
#define ST_R(i, v)  Y[rphys(i)] = (v)
        BF4(+1, LD_R, ST_R)
#undef LD_R
#undef ST_R
        __syncthreads();
        float2* tmp = X; X = Y; Y = tmp;
    }

    const float sc = 1.0f / 65536.0f;
    float* o = out + p * 512;
#pragma unroll
    for (int kk = 0; kk < 4; kk++) {
        int w = u + 64 * kk;
        float2 z = X[rphys(w)];
        o[w]       = z.x * sc;
        o[256 + w] = z.y * sc;
    }
}

// ---------------------------------------------------------------------------
extern "C" void kernel_launch(void* const* d_in, const int* in_sizes, int n_in,
                              void* d_out, int out_size)
{
    const float* x = (const float*)d_in[0];   // (16,32,256,256)
    const float* w = (const float*)d_in[1];   // (32,32,256,256)
    float* out = (float*)d_out;               // (16,32,256,256)

    float2 *pxf, *pkf, *pof;
    cudaGetSymbolAddress((void**)&pxf, g_xf);
    cudaGetSymbolAddress((void**)&pkf, g_kf);
    cudaGetSymbolAddress((void**)&pof, g_of);

    cudaFuncSetAttribute(pointwise_kernel,
                         cudaFuncAttributeMaxDynamicSharedMemorySize, 98560);

    // Forward rFFT along W (packed pairs, 4 pairs per block).
    rfft_rows_kernel<<<16384, 256>>>(x, pxf);
    rfft_rows_kernel<<<32768, 256>>>(w, pkf);

    // Forward FFT along H.
    fft_cols_kernel<-1><<<dim3(17, 512), 256>>>(pxf);
    fft_cols_kernel<-1><<<dim3(17, 1024), 256>>>(pkf);

    // Per-bin channel contraction.
    pointwise_kernel<<<4128, 256, 98560>>>(pxf, pkf, pof);

    // Inverse FFT along H + inverse rFFT along W.
    fft_cols_kernel<1><<<dim3(17, 512), 256>>>(pof);
    irfft_rows_kernel<<<16384, 256>>>(pof, out);
}

// round 3
// speedup vs baseline: 1.5233x; 1.2344x over previous
#include <cuda_runtime.h>

#define TWO_PI 6.283185307179586f

typedef unsigned long long u64;

__device__ __forceinline__ float2 cmulf(float2 a, float2 b) {
    return make_float2(fmaf(a.x, b.x, -a.y * b.y), fmaf(a.x, b.y, a.y * b.x));
}
__device__ __forceinline__ float2 cadd(float2 a, float2 b) { return make_float2(a.x+b.x, a.y+b.y); }
__device__ __forceinline__ float2 csub(float2 a, float2 b) { return make_float2(a.x-b.x, a.y-b.y); }
__device__ __forceinline__ float2 mulc(float2 z, float cr, float ci) {
    return make_float2(fmaf(z.x, cr, -z.y * ci), fmaf(z.x, ci, z.y * cr));
}

// padded smem index for row-FFT buffers (≤2-way banks on all stages)
__device__ __forceinline__ int rphys(int i) { return i + 5 * (i >> 4); }

__device__ __forceinline__ u64 pk2(float lo, float hi) {
    u64 r; asm("mov.b64 %0, {%1, %2};" : "=l"(r) : "f"(lo), "f"(hi)); return r;
}
__device__ __forceinline__ u64 ffma2(u64 a, u64 b, u64 c) {
    u64 d; asm("fma.rn.f32x2 %0, %1, %2, %3;" : "=l"(d) : "l"(a), "l"(b), "l"(c)); return d;
}
__device__ __forceinline__ float2 upk2(u64 v) {
    float x, y; asm("mov.b64 {%0, %1}, %2;" : "=f"(x), "=f"(y) : "l"(v)); return make_float2(x, y);
}

// Scratch frequency-domain tensors.
__device__ float2 g_xf[16908288];   // (16*32) x 256 x 129
__device__ float2 g_kf[33816576];   // (32*32) x 256 x 129
__device__ float2 g_of[16908288];   // (16*32) x 256 x 129

// ---------------------------------------------------------------------------
// 4-point DFT, W4 = e^{SIGN*i*2pi/4}.
// ---------------------------------------------------------------------------
template <int SIGN>
__device__ __forceinline__ void dft4(float2 a, float2 b, float2 c, float2 d,
                                     float2& y0, float2& y1, float2& y2, float2& y3)
{
    float2 t0 = cadd(a, c), t1 = csub(a, c);
    float2 t2 = cadd(b, d), t3 = csub(b, d);
    float2 w3 = (SIGN < 0) ? make_float2(t3.y, -t3.x) : make_float2(-t3.y, t3.x);
    y0 = cadd(t0, t2); y2 = csub(t0, t2);
    y1 = cadd(t1, w3); y3 = csub(t1, w3);
}

// ---------------------------------------------------------------------------
// 16-point DFT in registers (radix-4 x radix-4), natural order in/out.
// X[k] = sum_n r[n] e^{SIGN*i*2pi*n*k/16}
// ---------------------------------------------------------------------------
template <int SIGN>
__device__ __forceinline__ void dft16(float2 r[16])
{
    const float C1 = 0.9238795325112867f;   // cos(pi/8)
    const float S1 = 0.3826834323650898f;   // sin(pi/8)
    const float C2 = 0.7071067811865476f;   // cos(pi/4)
    const float sg = (float)SIGN;

    float2 A[16];
#pragma unroll
    for (int n2 = 0; n2 < 4; n2++)
        dft4<SIGN>(r[n2], r[4 + n2], r[8 + n2], r[12 + n2],
                   A[n2 * 4 + 0], A[n2 * 4 + 1], A[n2 * 4 + 2], A[n2 * 4 + 3]);

    // W16^{n2*k1}
    A[4 + 1]  = mulc(A[4 + 1],  C1,  sg * S1);
    A[4 + 2]  = mulc(A[4 + 2],  C2,  sg * C2);
    A[4 + 3]  = mulc(A[4 + 3],  S1,  sg * C1);
    A[8 + 1]  = mulc(A[8 + 1],  C2,  sg * C2);
    A[8 + 2]  = (SIGN < 0) ? make_float2(A[8 + 2].y, -A[8 + 2].x)
                           : make_float2(-A[8 + 2].y, A[8 + 2].x);
    A[8 + 3]  = mulc(A[8 + 3], -C2,  sg * C2);
    A[12 + 1] = mulc(A[12 + 1], S1,  sg * C1);
    A[12 + 2] = mulc(A[12 + 2], -C2, sg * C2);
    A[12 + 3] = mulc(A[12 + 3], -C1, -sg * S1);

#pragma unroll
    for (int k1 = 0; k1 < 4; k1++)
        dft4<SIGN>(A[k1], A[4 + k1], A[8 + k1], A[12 + k1],
                   r[k1], r[k1 + 4], r[k1 + 8], r[k1 + 12]);
}

// ---------------------------------------------------------------------------
// Fused radix-4 Stockham stage (used by the row kernels).
// ---------------------------------------------------------------------------
#define BF4(SIGN, LOAD, STORE)                                                 \
    {                                                                          \
        const int q  = u & (s - 1);                                            \
        const int ps = u - q;                                                  \
        float2 w1 = tw[ps], w2 = tw[2 * ps];                                   \
        float2 a1 = LOAD(u), a2 = LOAD(u + 64);                                \
        float2 b1 = LOAD(u + 128), b2 = LOAD(u + 192);                         \
        float2 u0 = cadd(a1, b1), u1 = cmulf(csub(a1, b1), w1);                \
        float2 v0 = cadd(a2, b2), v1 = cmulf(csub(a2, b2), w1);                \
        v1 = (SIGN < 0) ? make_float2(v1.y, -v1.x)                             \
                        : make_float2(-v1.y, v1.x);                            \
        const int ob = u + 3 * ps;                                             \
        STORE(ob,          cadd(u0, v0));                                      \
        STORE(ob + s,      cadd(u1, v1));                                      \
        STORE(ob + 2 * s,  cmulf(csub(u0, v0), w2));                           \
        STORE(ob + 3 * s,  cmulf(csub(u1, v1), w2));                           \
    }

// ---------------------------------------------------------------------------
// Forward real FFT along W: 4 packed row-pairs per block (256 threads).
// ---------------------------------------------------------------------------
__global__ void __launch_bounds__(256) rfft_rows_kernel(
    const float* __restrict__ in, float2* __restrict__ out)
{
    __shared__ float2 bufA[4][336], bufB[4][336];
    __shared__ float2 tw[128];
    const int t = threadIdx.x;
    const int f = t >> 6, u = t & 63;

    if (t < 128) {
        float s, c;
        sincosf(-TWO_PI * (float)t / 256.0f, &s, &c);
        tw[t] = make_float2(c, s);
    }

    const long p = (long)blockIdx.x * 4 + f;
    const float* r = in + p * 512;
#pragma unroll
    for (int k = 0; k < 4; k++) {
        int w = u + 64 * k;
        bufA[f][rphys(w)] = make_float2(r[w], r[256 + w]);
    }
    __syncthreads();

    float2 *X = bufA[f], *Y = bufB[f];
#pragma unroll
    for (int st = 0; st < 4; st++) {
        const int s = 1 << (2 * st);
#define LD_R(i)     X[rphys(i)]
#define ST_R(i, v)  Y[rphys(i)] = (v)
        BF4(-1, LD_R, ST_R)
#undef LD_R
#undef ST_R
        __syncthreads();
        float2* tmp = X; X = Y; Y = tmp;
    }

    float2* o = out + p * 258;
    for (int k = u; k < 129; k += 64) {
        float2 zk = X[rphys(k)];
        float2 zm = X[rphys((256 - k) & 255)];
        o[k]       = make_float2(0.5f * (zk.x + zm.x),  0.5f * (zk.y - zm.y));
        o[129 + k] = make_float2(0.5f * (zk.y + zm.y), -0.5f * (zk.x - zm.x));
    }
}

// ---------------------------------------------------------------------------
// Complex FFT along H: 16x16 register Cooley-Tukey, 16 columns per block.
// Thread (c = t&15, j = t>>4) handles column col0+c, time strides 16n1+j.
// One smem transpose round-trip, 2 barriers.
// ---------------------------------------------------------------------------
template <int SIGN>
__global__ void __launch_bounds__(256) fft_cols_kernel(float2* __restrict__ data)
{
    __shared__ float2 tr[4096];   // [ (e)*16 + c ], e = k1*16 + n2
    __shared__ float2 tw[256];
    const int t = threadIdx.x;
    const int c = t & 15, j = t >> 4;

    {
        float s, cc;
        sincosf((float)SIGN * TWO_PI * (float)t / 256.0f, &s, &cc);
        tw[t] = make_float2(cc, s);
    }

    float2* img = data + (size_t)blockIdx.y * 33024;
    const int col = blockIdx.x * 16 + c;
    const bool valid = (col < 129);

    float2 r[16];
#pragma unroll
    for (int n1 = 0; n1 < 16; n1++)
        r[n1] = valid ? img[(n1 * 16 + j) * 129 + col] : make_float2(0.f, 0.f);

    dft16<SIGN>(r);            // over n1 -> A[k1], k1 = 0..15
    __syncthreads();           // twiddle table ready

#pragma unroll
    for (int k1 = 0; k1 < 16; k1++) {
        if (k1) r[k1] = cmulf(r[k1], tw[j * k1]);   // W256^{j*k1}
        tr[(k1 * 16 + j) * 16 + c] = r[k1];
    }
    __syncthreads();

    float2 d[16];
#pragma unroll
    for (int n2 = 0; n2 < 16; n2++)
        d[n2] = tr[(j * 16 + n2) * 16 + c];

    dft16<SIGN>(d);            // over n2 -> X[j + 16*k2]

    if (valid) {
#pragma unroll
        for (int k2 = 0; k2 < 16; k2++)
            img[(j + 16 * k2) * 129 + col] = d[k2];
    }
}

// ---------------------------------------------------------------------------
// Pointwise frequency contraction with packed f32x2 FMA.
// ---------------------------------------------------------------------------
__global__ void __launch_bounds__(256) pointwise_kernel(
    const float2* __restrict__ xf, const float2* __restrict__ kf,
    float2* __restrict__ of)
{
    extern __shared__ float2 sm[];
    float2* xs = sm;          // 16 * 258 float2 (padded)
    float2* ks = sm + 4128;   // 32*32*8 float2
    const int t = threadIdx.x;
    const long f0 = (long)blockIdx.x * 8;

    for (int idx = t; idx < 4096; idx += 256) {
        int row = idx >> 3, fi = idx & 7;
        int b = row >> 5, cc = row & 31;
        xs[b * 258 + cc * 8 + fi] = xf[(size_t)row * 33024 + f0 + fi];
    }
    for (int idx = t; idx < 8192; idx += 256) {
        ks[idx] = kf[(size_t)(idx >> 3) * 33024 + f0 + (idx & 7)];
    }
    __syncthreads();

    const int fi = t & 7;
    const int g  = t >> 3;
    const int b0 = (g & 3) * 4;
    const int o0 = (g >> 2) * 4;

    u64 acc[4][4];
#pragma unroll
    for (int i = 0; i < 4; i++)
#pragma unroll
        for (int j = 0; j < 4; j++) acc[i][j] = 0ULL;

    for (int cc = 0; cc < 32; cc++) {
        u64 xa[4], xb[4], ka[4], kb[4];
#pragma unroll
        for (int i = 0; i < 4; i++) {
            float2 xv = xs[(b0 + i) * 258 + cc * 8 + fi];
            xa[i] = pk2(xv.x, xv.x);
            xb[i] = pk2(-xv.y, xv.y);
        }
#pragma unroll
        for (int j = 0; j < 4; j++) {
            float2 kv = ks[((o0 + j) * 32 + cc) * 8 + fi];
            ka[j] = pk2(kv.x, kv.y);
            kb[j] = pk2(kv.y, kv.x);
        }
#pragma unroll
        for (int i = 0; i < 4; i++)
#pragma unroll
            for (int j = 0; j < 4; j++) {
                acc[i][j] = ffma2(xa[i], ka[j], acc[i][j]);
                acc[i][j] = ffma2(xb[i], kb[j], acc[i][j]);
            }
    }

#pragma unroll
    for (int i = 0; i < 4; i++)
#pragma unroll
        for (int j = 0; j < 4; j++)
            of[(size_t)((b0 + i) * 32 + (o0 + j)) * 33024 + f0 + fi] = upk2(acc[i][j]);
}

// ---------------------------------------------------------------------------
// Inverse real FFT along W: 4 row-pairs per block, with 1/(H*W) scaling.
// ---------------------------------------------------------------------------
__global__ void __launch_bounds__(256) irfft_rows_kernel(
    const float2* __restrict__ in, float* __restrict__ out)
{
    __shared__ float2 bufA[4][336], bufB[4][336];
    __shared__ float2 tw[128];
    const int t = threadIdx.x;
    const int f = t >> 6, u = t & 63;

    if (t < 128) {
        float s, c;
        sincosf(TWO_PI * (float)t / 256.0f, &s, &c);
        tw[t] = make_float2(c, s);
    }

    const long p = (long)blockIdx.x * 4 + f;
    const float2* X0 = in + p * 258;
    const float2* X1 = X0 + 129;
#pragma unroll
    for (int kk = 0; kk < 4; kk++) {
        int k = u + 64 * kk;
        float2 a, b;
        if (k <= 128) { a = X0[k]; b = X1[k]; }
        else {
            float2 a0 = X0[256 - k]; a = make_float2(a0.x, -a0.y);
            float2 b0 = X1[256 - k]; b = make_float2(b0.x, -b0.y);
        }
        bufA[f][rphys(k)] = make_float2(a.x - b.y, a.y + b.x);
    }
    __syncthreads();

    float2 *X = bufA[f], *Y = bufB[f];
#pragma unroll
    for (int st = 0; st < 4; st++) {
        const int s = 1 << (2 * st);
#define LD_R(i)     X[rphys(i)]
#define ST_R(i, v)  Y[rphys(i)] = (v)
        BF4(+1, LD_R, ST_R)
#undef LD_R
#undef ST_R
        __syncthreads();
        float2* tmp = X; X = Y; Y = tmp;
    }

    const float sc = 1.0f / 65536.0f;
    float* o = out + p * 512;
#pragma unroll
    for (int kk = 0; kk < 4; kk++) {
        int w = u + 64 * kk;
        float2 z = X[rphys(w)];
        o[w]       = z.x * sc;
        o[256 + w] = z.y * sc;
    }
}

// ---------------------------------------------------------------------------
extern "C" void kernel_launch(void* const* d_in, const int* in_sizes, int n_in,
                              void* d_out, int out_size)
{
    const float* x = (const float*)d_in[0];   // (16,32,256,256)
    const float* w = (const float*)d_in[1];   // (32,32,256,256)
    float* out = (float*)d_out;               // (16,32,256,256)

    float2 *pxf, *pkf, *pof;
    cudaGetSymbolAddress((void**)&pxf, g_xf);
    cudaGetSymbolAddress((void**)&pkf, g_kf);
    cudaGetSymbolAddress((void**)&pof, g_of);

    cudaFuncSetAttribute(pointwise_kernel,
                         cudaFuncAttributeMaxDynamicSharedMemorySize, 98560);

    // Forward rFFT along W (packed pairs, 4 pairs per block).
    rfft_rows_kernel<<<16384, 256>>>(x, pxf);
    rfft_rows_kernel<<<32768, 256>>>(w, pkf);

    // Forward FFT along H: 16x16 register FFT, 16 cols/block, 9 blocks per image.
    fft_cols_kernel<-1><<<dim3(9, 512), 256>>>(pxf);
    fft_cols_kernel<-1><<<dim3(9, 1024), 256>>>(pkf);

    // Per-bin channel contraction.
    pointwise_kernel<<<4128, 256, 98560>>>(pxf, pkf, pof);

    // Inverse FFT along H + inverse rFFT along W.
    fft_cols_kernel<1><<<dim3(9, 512), 256>>>(pof);
    irfft_rows_kernel<<<16384, 256>>>(pof, out);
}

// round 4
// speedup vs baseline: 2.0302x; 1.3328x over previous
#include <cuda_runtime.h>
#include <cuda_fp16.h>

#define TWO_PI 6.283185307179586f

typedef unsigned long long u64;

__device__ __forceinline__ float2 cmulf(float2 a, float2 b) {
    return make_float2(fmaf(a.x, b.x, -a.y * b.y), fmaf(a.x, b.y, a.y * b.x));
}
__device__ __forceinline__ float2 cadd(float2 a, float2 b) { return make_float2(a.x+b.x, a.y+b.y); }
__device__ __forceinline__ float2 csub(float2 a, float2 b) { return make_float2(a.x-b.x, a.y-b.y); }
__device__ __forceinline__ float2 mulc(float2 z, float cr, float ci) {
    return make_float2(fmaf(z.x, cr, -z.y * ci), fmaf(z.x, ci, z.y * cr));
}
__device__ __forceinline__ float2 h2f(__half2 h) { return __half22float2(h); }
__device__ __forceinline__ __half2 f2h(float2 f) { return __float22half2_rn(f); }

__device__ __forceinline__ u64 pk2(float lo, float hi) {
    u64 r; asm("mov.b64 %0, {%1, %2};" : "=l"(r) : "f"(lo), "f"(hi)); return r;
}
__device__ __forceinline__ u64 ffma2(u64 a, u64 b, u64 c) {
    u64 d; asm("fma.rn.f32x2 %0, %1, %2, %3;" : "=l"(d) : "l"(a), "l"(b), "l"(c)); return d;
}
__device__ __forceinline__ float2 upk2(u64 v) {
    float x, y; asm("mov.b64 {%0, %1}, %2;" : "=f"(x), "=f"(y) : "l"(v)); return make_float2(x, y);
}

// Frequency-domain scratch in fp16 (half traffic vs fp32).
__device__ __half2 g_xf[16908288];   // (16*32) x 256 x 129
__device__ __half2 g_kf[33816576];   // (32*32) x 256 x 129
__device__ __half2 g_of[16908288];   // (16*32) x 256 x 129

// ---------------------------------------------------------------------------
// 4-point / 16-point register DFTs.
// ---------------------------------------------------------------------------
template <int SIGN>
__device__ __forceinline__ void dft4(float2 a, float2 b, float2 c, float2 d,
                                     float2& y0, float2& y1, float2& y2, float2& y3)
{
    float2 t0 = cadd(a, c), t1 = csub(a, c);
    float2 t2 = cadd(b, d), t3 = csub(b, d);
    float2 w3 = (SIGN < 0) ? make_float2(t3.y, -t3.x) : make_float2(-t3.y, t3.x);
    y0 = cadd(t0, t2); y2 = csub(t0, t2);
    y1 = cadd(t1, w3); y3 = csub(t1, w3);
}

template <int SIGN>
__device__ __forceinline__ void dft16(float2 r[16])
{
    const float C1 = 0.9238795325112867f;
    const float S1 = 0.3826834323650898f;
    const float C2 = 0.7071067811865476f;
    const float sg = (float)SIGN;

    float2 A[16];
#pragma unroll
    for (int n2 = 0; n2 < 4; n2++)
        dft4<SIGN>(r[n2], r[4 + n2], r[8 + n2], r[12 + n2],
                   A[n2 * 4 + 0], A[n2 * 4 + 1], A[n2 * 4 + 2], A[n2 * 4 + 3]);

    A[4 + 1]  = mulc(A[4 + 1],  C1,  sg * S1);
    A[4 + 2]  = mulc(A[4 + 2],  C2,  sg * C2);
    A[4 + 3]  = mulc(A[4 + 3],  S1,  sg * C1);
    A[8 + 1]  = mulc(A[8 + 1],  C2,  sg * C2);
    A[8 + 2]  = (SIGN < 0) ? make_float2(A[8 + 2].y, -A[8 + 2].x)
                           : make_float2(-A[8 + 2].y, A[8 + 2].x);
    A[8 + 3]  = mulc(A[8 + 3], -C2,  sg * C2);
    A[12 + 1] = mulc(A[12 + 1], S1,  sg * C1);
    A[12 + 2] = mulc(A[12 + 2], -C2, sg * C2);
    A[12 + 3] = mulc(A[12 + 3], -C1, -sg * S1);

#pragma unroll
    for (int k1 = 0; k1 < 4; k1++)
        dft4<SIGN>(A[k1], A[4 + k1], A[8 + k1], A[12 + k1],
                   r[k1], r[k1 + 4], r[k1 + 8], r[k1 + 12]);
}

// padded linear smem index (2-FFT-per-warp transpose regions)
__device__ __forceinline__ int zpad(int k) { return k + (k >> 4); }

// ---------------------------------------------------------------------------
// Forward real FFT along W: 16 packed row-pairs per block, 16 threads per FFT.
// Thread (f = t>>4, j = t&15). One transpose + one unpack stage in smem.
// ---------------------------------------------------------------------------
__global__ void __launch_bounds__(256) rfft_rows_kernel(
    const float* __restrict__ in, __half2* __restrict__ out)
{
    __shared__ float2 tr[16][272];
    __shared__ float2 tw[256];
    const int t = threadIdx.x;
    const int f = t >> 4, j = t & 15;

    {
        float s, c;
        sincosf(-TWO_PI * (float)t / 256.0f, &s, &c);
        tw[t] = make_float2(c, s);
    }

    const long p = (long)blockIdx.x * 16 + f;
    const float* rp = in + p * 512;

    float2 r[16];
#pragma unroll
    for (int n1 = 0; n1 < 16; n1++)
        r[n1] = make_float2(rp[n1 * 16 + j], rp[256 + n1 * 16 + j]);

    dft16<-1>(r);              // over n1 -> index k1
    __syncthreads();           // tw ready

#pragma unroll
    for (int k1 = 0; k1 < 16; k1++) {
        if (k1) r[k1] = cmulf(r[k1], tw[j * k1]);
        tr[f][k1 * 17 + j] = r[k1];
    }
    __syncthreads();

    float2 d[16];
#pragma unroll
    for (int n2 = 0; n2 < 16; n2++)
        d[n2] = tr[f][j * 17 + n2];

    dft16<-1>(d);              // final Z[j + 16*k2]
    __syncthreads();

#pragma unroll
    for (int k2 = 0; k2 < 16; k2++)
        tr[f][zpad(j + 16 * k2)] = d[k2];
    __syncthreads();

    // Unpack two real spectra and store fp16.
    __half2* o = out + p * 258;
#pragma unroll
    for (int k2 = 0; k2 < 9; k2++) {
        int k = j + 16 * k2;
        if (k <= 128) {
            float2 zk = tr[f][zpad(k)];
            float2 zm = tr[f][zpad((256 - k) & 255)];
            o[k]       = f2h(make_float2(0.5f * (zk.x + zm.x),  0.5f * (zk.y - zm.y)));
            o[129 + k] = f2h(make_float2(0.5f * (zk.y + zm.y), -0.5f * (zk.x - zm.x)));
        }
    }
}

// ---------------------------------------------------------------------------
// Complex FFT along H: 16x16 register Cooley-Tukey, 16 columns per block.
// ---------------------------------------------------------------------------
template <int SIGN>
__global__ void __launch_bounds__(256) fft_cols_kernel(__half2* __restrict__ data)
{
    __shared__ float2 tr[4096];
    __shared__ float2 tw[256];
    const int t = threadIdx.x;
    const int c = t & 15, j = t >> 4;

    {
        float s, cc;
        sincosf((float)SIGN * TWO_PI * (float)t / 256.0f, &s, &cc);
        tw[t] = make_float2(cc, s);
    }

    __half2* img = data + (size_t)blockIdx.y * 33024;
    const int col = blockIdx.x * 16 + c;
    const bool valid = (col < 129);

    float2 r[16];
#pragma unroll
    for (int n1 = 0; n1 < 16; n1++)
        r[n1] = valid ? h2f(img[(n1 * 16 + j) * 129 + col]) : make_float2(0.f, 0.f);

    dft16<SIGN>(r);
    __syncthreads();

#pragma unroll
    for (int k1 = 0; k1 < 16; k1++) {
        if (k1) r[k1] = cmulf(r[k1], tw[j * k1]);
        tr[(k1 * 16 + j) * 16 + c] = r[k1];
    }
    __syncthreads();

    float2 d[16];
#pragma unroll
    for (int n2 = 0; n2 < 16; n2++)
        d[n2] = tr[(j * 16 + n2) * 16 + c];

    dft16<SIGN>(d);

    if (valid) {
#pragma unroll
        for (int k2 = 0; k2 < 16; k2++)
            img[(j + 16 * k2) * 129 + col] = f2h(d[k2]);
    }
}

// ---------------------------------------------------------------------------
// Pointwise frequency contraction with packed f32x2 FMA (fp16 I/O, fp32 math).
// ---------------------------------------------------------------------------
__global__ void __launch_bounds__(256) pointwise_kernel(
    const __half2* __restrict__ xf, const __half2* __restrict__ kf,
    __half2* __restrict__ of)
{
    extern __shared__ float2 sm[];
    float2* xs = sm;          // 16 * 258 float2 (padded)
    float2* ks = sm + 4128;   // 32*32*8 float2
    const int t = threadIdx.x;
    const long f0 = (long)blockIdx.x * 8;

    for (int idx = t; idx < 4096; idx += 256) {
        int row = idx >> 3, fi = idx & 7;
        int b = row >> 5, cc = row & 31;
        xs[b * 258 + cc * 8 + fi] = h2f(xf[(size_t)row * 33024 + f0 + fi]);
    }
    for (int idx = t; idx < 8192; idx += 256) {
        ks[idx] = h2f(kf[(size_t)(idx >> 3) * 33024 + f0 + (idx & 7)]);
    }
    __syncthreads();

    const int fi = t & 7;
    const int g  = t >> 3;
    const int b0 = (g & 3) * 4;
    const int o0 = (g >> 2) * 4;

    u64 acc[4][4];
#pragma unroll
    for (int i = 0; i < 4; i++)
#pragma unroll
        for (int j = 0; j < 4; j++) acc[i][j] = 0ULL;

    for (int cc = 0; cc < 32; cc++) {
        u64 xa[4], xb[4], ka[4], kb[4];
#pragma unroll
        for (int i = 0; i < 4; i++) {
            float2 xv = xs[(b0 + i) * 258 + cc * 8 + fi];
            xa[i] = pk2(xv.x, xv.x);
            xb[i] = pk2(-xv.y, xv.y);
        }
#pragma unroll
        for (int j = 0; j < 4; j++) {
            float2 kv = ks[((o0 + j) * 32 + cc) * 8 + fi];
            ka[j] = pk2(kv.x, kv.y);
            kb[j] = pk2(kv.y, kv.x);
        }
#pragma unroll
        for (int i = 0; i < 4; i++)
#pragma unroll
            for (int j = 0; j < 4; j++) {
                acc[i][j] = ffma2(xa[i], ka[j], acc[i][j]);
                acc[i][j] = ffma2(xb[i], kb[j], acc[i][j]);
            }
    }

#pragma unroll
    for (int i = 0; i < 4; i++)
#pragma unroll
        for (int j = 0; j < 4; j++)
            of[(size_t)((b0 + i) * 32 + (o0 + j)) * 33024 + f0 + fi] = f2h(upk2(acc[i][j]));
}

// ---------------------------------------------------------------------------
// Inverse real FFT along W: 16 row-pairs per block, register 16x16 FFT.
// ---------------------------------------------------------------------------
__global__ void __launch_bounds__(256) irfft_rows_kernel(
    const __half2* __restrict__ in, float* __restrict__ out)
{
    __shared__ float2 tr[16][272];
    __shared__ float2 tw[256];
    const int t = threadIdx.x;
    const int f = t >> 4, j = t & 15;

    {
        float s, c;
        sincosf(TWO_PI * (float)t / 256.0f, &s, &c);
        tw[t] = make_float2(c, s);
    }

    const long p = (long)blockIdx.x * 16 + f;
    const __half2* X0 = in + p * 258;
    const __half2* X1 = X0 + 129;

    float2 r[16];
#pragma unroll
    for (int a = 0; a < 16; a++) {
        int k = a * 16 + j;
        float2 av, bv;
        if (k <= 128) { av = h2f(X0[k]); bv = h2f(X1[k]); }
        else {
            float2 a0 = h2f(X0[256 - k]); av = make_float2(a0.x, -a0.y);
            float2 b0 = h2f(X1[256 - k]); bv = make_float2(b0.x, -b0.y);
        }
        r[a] = make_float2(av.x - bv.y, av.y + bv.x);
    }

    dft16<1>(r);
    __syncthreads();

#pragma unroll
    for (int k1 = 0; k1 < 16; k1++) {
        if (k1) r[k1] = cmulf(r[k1], tw[j * k1]);
        tr[f][k1 * 17 + j] = r[k1];
    }
    __syncthreads();

    float2 d[16];
#pragma unroll
    for (int n2 = 0; n2 < 16; n2++)
        d[n2] = tr[f][j * 17 + n2];

    dft16<1>(d);               // z[j + 16*k2]

    const float sc = 1.0f / 65536.0f;
    float* o = out + p * 512;
#pragma unroll
    for (int k2 = 0; k2 < 16; k2++) {
        int n = j + 16 * k2;
        o[n]       = d[k2].x * sc;
        o[256 + n] = d[k2].y * sc;
    }
}

// ---------------------------------------------------------------------------
extern "C" void kernel_launch(void* const* d_in, const int* in_sizes, int n_in,
                              void* d_out, int out_size)
{
    const float* x = (const float*)d_in[0];   // (16,32,256,256)
    const float* w = (const float*)d_in[1];   // (32,32,256,256)
    float* out = (float*)d_out;               // (16,32,256,256)

    __half2 *pxf, *pkf, *pof;
    cudaGetSymbolAddress((void**)&pxf, g_xf);
    cudaGetSymbolAddress((void**)&pkf, g_kf);
    cudaGetSymbolAddress((void**)&pof, g_of);

    cudaFuncSetAttribute(pointwise_kernel,
                         cudaFuncAttributeMaxDynamicSharedMemorySize, 98560);

    // Forward rFFT along W (packed pairs, 16 pairs per block).
    rfft_rows_kernel<<<4096, 256>>>(x, pxf);
    rfft_rows_kernel<<<8192, 256>>>(w, pkf);

    // Forward FFT along H.
    fft_cols_kernel<-1><<<dim3(9, 512), 256>>>(pxf);
    fft_cols_kernel<-1><<<dim3(9, 1024), 256>>>(pkf);

    // Per-bin channel contraction.
    pointwise_kernel<<<4128, 256, 98560>>>(pxf, pkf, pof);

    // Inverse FFT along H + inverse rFFT along W.
    fft_cols_kernel<1><<<dim3(9, 512), 256>>>(pof);
    irfft_rows_kernel<<<4096, 256>>>(pof, out);
}